// round 1
// baseline (speedup 1.0000x reference)
#include <cuda_runtime.h>
#include <cstdint>

#define N_SP 4096
#define C_CH 512
#define M_QK 64
#define B_SZ 4

typedef unsigned long long u64;

// Scratch (device globals, allocation-free): q,k in [B][M][N], v in [B][N][C]
__device__ float g_q[B_SZ * M_QK * N_SP];
__device__ float g_k[B_SZ * M_QK * N_SP];
__device__ float g_v[(size_t)B_SZ * N_SP * C_CH];

__device__ __forceinline__ u64 pk2(float x, float y) {
    u64 r; asm("mov.b64 %0, {%1,%2};" : "=l"(r) : "f"(x), "f"(y)); return r;
}
__device__ __forceinline__ void upk2(u64 v, float& x, float& y) {
    asm("mov.b64 {%0,%1}, %2;" : "=f"(x), "=f"(y) : "l"(v));
}
__device__ __forceinline__ u64 fma2(u64 a, u64 b, u64 c) {
    u64 d; asm("fma.rn.f32x2 %0, %1, %2, %3;" : "=l"(d) : "l"(a), "l"(b), "l"(c)); return d;
}
__device__ __forceinline__ u64 mul2(u64 a, u64 b) {
    u64 d; asm("mul.rn.f32x2 %0, %1, %2;" : "=l"(d) : "l"(a), "l"(b)); return d;
}
__device__ __forceinline__ uint32_t s2u(const void* p) {
    return (uint32_t)__cvta_generic_to_shared(p);
}
__device__ __forceinline__ void cp16(uint32_t d, const void* s) {
    asm volatile("cp.async.cg.shared.global [%0], [%1], 16;" :: "r"(d), "l"(s));
}
__device__ __forceinline__ void cp_commit() { asm volatile("cp.async.commit_group;"); }
__device__ __forceinline__ void cp_wait0()  { asm volatile("cp.async.wait_group 0;"); }

// ---------------------------------------------------------------------------
// Projection GEMM: out = W[Md,C] @ x[b][C][N] + bias
// TRANS=1: out[b][m][n] (for q,k).  TRANS=0: out[b][n][m] (for v).
// Block: 64n x 64m tile, 256 threads, micro 4n x 4m via f32x2.
// ---------------------------------------------------------------------------
template<int TRANS>
__global__ __launch_bounds__(256) void proj_kernel(
    const float* __restrict__ x, const float* __restrict__ W,
    const float* __restrict__ bias, float* __restrict__ out, int Md)
{
    __shared__ float Ws[32][66];   // [c][m], pad 66 keeps 8B alignment of pairs
    __shared__ float Xs[32][64];   // [c][n]
    int t  = threadIdx.x;
    int tx = t & 15, ty = t >> 4;
    int n0 = blockIdx.x * 64, m0 = blockIdx.y * 64, b = blockIdx.z;

    u64 acc[4][2];
#pragma unroll
    for (int i = 0; i < 4; i++)
#pragma unroll
        for (int p = 0; p < 2; p++) acc[i][p] = 0ull;

    const float* xb = x + (size_t)b * C_CH * N_SP;

    for (int cc = 0; cc < C_CH; cc += 32) {
#pragma unroll
        for (int k = 0; k < 8; k++) {
            int idx = t + k * 256;
            int m = idx >> 5, c = idx & 31;
            Ws[c][m] = W[(size_t)(m0 + m) * C_CH + cc + c];
        }
#pragma unroll
        for (int k = 0; k < 8; k++) {
            int idx = t + k * 256;
            int c = idx >> 6, n = idx & 63;
            Xs[c][n] = xb[(size_t)(cc + c) * N_SP + n0 + n];
        }
        __syncthreads();
#pragma unroll
        for (int c = 0; c < 32; c++) {
            u64 w0 = *(const u64*)&Ws[c][tx * 4];
            u64 w1 = *(const u64*)&Ws[c][tx * 4 + 2];
#pragma unroll
            for (int i = 0; i < 4; i++) {
                float xv = Xs[c][ty * 4 + i];
                u64 xd = pk2(xv, xv);
                acc[i][0] = fma2(xd, w0, acc[i][0]);
                acc[i][1] = fma2(xd, w1, acc[i][1]);
            }
        }
        __syncthreads();
    }

    float av[4][4];
#pragma unroll
    for (int i = 0; i < 4; i++) {
        upk2(acc[i][0], av[i][0], av[i][1]);
        upk2(acc[i][1], av[i][2], av[i][3]);
    }
    float bv[4];
#pragma unroll
    for (int j = 0; j < 4; j++) bv[j] = bias[m0 + tx * 4 + j];

    if (TRANS) {
        // out[b][m][n] : for each m, 4 consecutive n -> float4
#pragma unroll
        for (int j = 0; j < 4; j++) {
            float4 o;
            o.x = av[0][j] + bv[j]; o.y = av[1][j] + bv[j];
            o.z = av[2][j] + bv[j]; o.w = av[3][j] + bv[j];
            *(float4*)&out[((size_t)b * Md + m0 + tx * 4 + j) * N_SP + n0 + ty * 4] = o;
        }
    } else {
        // out[b][n][m] : for each n, 4 consecutive m -> float4
#pragma unroll
        for (int i = 0; i < 4; i++) {
            float4 o;
            o.x = av[i][0] + bv[0]; o.y = av[i][1] + bv[1];
            o.z = av[i][2] + bv[2]; o.w = av[i][3] + bv[3];
            *(float4*)&out[((size_t)b * N_SP + n0 + ty * 4 + i) * Md + m0 + tx * 4] = o;
        }
    }
}

// ---------------------------------------------------------------------------
// Fused attention: per block, 64 query positions of one batch. Online softmax
// over j-tiles of 32. Double-buffered cp.async for K/V tiles.
// acc[i][c] (64 rows x 512 cols per block) held as 32 f32x2 regs per thread.
// ---------------------------------------------------------------------------
__global__ __launch_bounds__(512, 1) void attn_kernel(
    const float* __restrict__ xin, const float* __restrict__ gamma,
    float* __restrict__ out)
{
    extern __shared__ float sm[];
    // float offsets
    const int VS  = 0;         // 2 x (32 x 512) V tiles
    const int KT  = 32768;     // 2 x (64m x 32j) K tiles
    const int QT  = 36864;     // 64m x 64i Q tile
    const int SS  = 40960;     // 64 x 33 scores / probs
    const int STM = 43072;     // running max [64]
    const int STL = 43136;     // running sum [64]
    const int STF = 43200;     // rescale factor / rinv [64]

    int t  = threadIdx.x;
    int b  = blockIdx.y;
    int i0 = blockIdx.x * 64;

    const float* qg = g_q + (size_t)b * M_QK * N_SP;
    const float* kg = g_k + (size_t)b * M_QK * N_SP;
    const float* vg = g_v + (size_t)b * N_SP * C_CH;

    if (t < 64) { sm[STM + t] = -1e30f; sm[STL + t] = 0.f; }

    uint32_t vs_u = s2u(sm + VS);
    uint32_t kt_u = s2u(sm + KT);
    uint32_t qt_u = s2u(sm + QT);

    // prologue: Q tile (transposed layout [m][i]) + j-tile 0
#pragma unroll
    for (int k = 0; k < 2; k++) {
        int z = t + k * 512;              // 1024 float4 chunks of 64x64
        int row = z >> 4, c4 = z & 15;
        cp16(qt_u + (row * 64 + c4 * 4) * 4, qg + (size_t)row * N_SP + i0 + c4 * 4);
    }
    {
        const float* vsrc = vg;           // j0 = 0, contiguous 64KB
#pragma unroll
        for (int k = 0; k < 8; k++) { int z = t + k * 512; cp16(vs_u + z * 16, vsrc + z * 4); }
        int m = t >> 3, c4 = t & 7;
        cp16(kt_u + (m * 32 + c4 * 4) * 4, kg + (size_t)m * N_SP + c4 * 4);
    }
    cp_commit();

    const int igrp = t >> 6, cgrp = t & 63;   // PV mapping
    const int i2   = t >> 4, j2   = t & 15;   // QK mapping
    const int r    = t >> 3, k8   = t & 7;    // softmax row mapping

    u64 acc[8][4];
#pragma unroll
    for (int ii = 0; ii < 8; ii++)
#pragma unroll
        for (int p = 0; p < 4; p++) acc[ii][p] = 0ull;

    const int NT = N_SP / 32;
    for (int it = 0; it < NT; ++it) {
        cp_wait0();
        __syncthreads();
        int buf = it & 1;

        if (it + 1 < NT) {
            int nb = buf ^ 1;
            int j0 = (it + 1) * 32;
            const float* vsrc = vg + (size_t)j0 * C_CH;
#pragma unroll
            for (int k = 0; k < 8; k++) {
                int z = t + k * 512;
                cp16(vs_u + (nb * 16384 + z * 4) * 4, vsrc + z * 4);
            }
            int m = t >> 3, c4 = t & 7;
            cp16(kt_u + (nb * 2048 + m * 32 + c4 * 4) * 4,
                 kg + (size_t)m * N_SP + j0 + c4 * 4);
            cp_commit();
        }

        // --- QK: each thread 2i x 2j dot products over m=64 ---
        {
            const float* KTb = sm + KT + buf * 2048;
            u64 a0 = 0ull, a1 = 0ull;
#pragma unroll
            for (int m = 0; m < 64; m++) {
                u64 k2 = *(const u64*)&KTb[m * 32 + j2 * 2];
                float2 q2 = *(const float2*)&sm[QT + m * 64 + i2 * 2];
                a0 = fma2(pk2(q2.x, q2.x), k2, a0);
                a1 = fma2(pk2(q2.y, q2.y), k2, a1);
            }
            float s00, s01, s10, s11;
            upk2(a0, s00, s01); upk2(a1, s10, s11);
            sm[SS + (i2 * 2 + 0) * 33 + j2 * 2 + 0] = s00;
            sm[SS + (i2 * 2 + 0) * 33 + j2 * 2 + 1] = s01;
            sm[SS + (i2 * 2 + 1) * 33 + j2 * 2 + 0] = s10;
            sm[SS + (i2 * 2 + 1) * 33 + j2 * 2 + 1] = s11;
        }
        __syncthreads();

        // --- online softmax row pass: 8 threads per row ---
        {
            float sv[4];
#pragma unroll
            for (int c = 0; c < 4; c++) sv[c] = sm[SS + r * 33 + k8 * 4 + c];
            float mx = fmaxf(fmaxf(sv[0], sv[1]), fmaxf(sv[2], sv[3]));
#pragma unroll
            for (int w = 1; w < 8; w <<= 1) mx = fmaxf(mx, __shfl_xor_sync(0xffffffffu, mx, w));
            float mold = sm[STM + r];
            float mnew = fmaxf(mold, mx);
            float f = __expf(mold - mnew);
            float ps = 0.f;
#pragma unroll
            for (int c = 0; c < 4; c++) {
                float p = __expf(sv[c] - mnew);
                sm[SS + r * 33 + k8 * 4 + c] = p;
                ps += p;
            }
#pragma unroll
            for (int w = 1; w < 8; w <<= 1) ps += __shfl_xor_sync(0xffffffffu, ps, w);
            if (k8 == 0) {
                sm[STL + r] = sm[STL + r] * f + ps;
                sm[STM + r] = mnew;
                sm[STF + r] = f;
            }
        }
        __syncthreads();

        // --- rescale accumulators ---
#pragma unroll
        for (int ii = 0; ii < 8; ii++) {
            float f = sm[STF + igrp * 8 + ii];
            u64 fd = pk2(f, f);
#pragma unroll
            for (int p = 0; p < 4; p++) acc[ii][p] = mul2(acc[ii][p], fd);
        }

        // --- PV: acc[i][c] += p[i][j] * v[j][c] ---
        {
            const float* VSb = sm + VS + buf * 16384;
            const float* PS  = sm + SS;
            for (int j = 0; j < 32; j++) {
                u64 v0 = *(const u64*)&VSb[j * 512 + cgrp * 2 + 0 * 128];
                u64 v1 = *(const u64*)&VSb[j * 512 + cgrp * 2 + 1 * 128];
                u64 v2 = *(const u64*)&VSb[j * 512 + cgrp * 2 + 2 * 128];
                u64 v3 = *(const u64*)&VSb[j * 512 + cgrp * 2 + 3 * 128];
#pragma unroll
                for (int ii = 0; ii < 8; ii++) {
                    float p = PS[(igrp * 8 + ii) * 33 + j];
                    u64 pd = pk2(p, p);
                    acc[ii][0] = fma2(pd, v0, acc[ii][0]);
                    acc[ii][1] = fma2(pd, v1, acc[ii][1]);
                    acc[ii][2] = fma2(pd, v2, acc[ii][2]);
                    acc[ii][3] = fma2(pd, v3, acc[ii][3]);
                }
            }
        }
    }

    // --- epilogue: out[b][c][n] = gamma * acc/l + x, smem-transposed stores ---
    __syncthreads();
    float gam = gamma[0];
    if (t < 64) sm[STF + t] = gam / sm[STL + t];
    __syncthreads();
    float rinv[8];
#pragma unroll
    for (int ii = 0; ii < 8; ii++) rinv[ii] = sm[STF + igrp * 8 + ii];

#pragma unroll
    for (int pass = 0; pass < 2; pass++) {
        if (pass) __syncthreads();
        // stage 256 c-rows x 64 i into [cl][65] buffer (aliases VS region)
#pragma unroll
        for (int p2 = 0; p2 < 2; p2++) {
            int p = pass * 2 + p2;
#pragma unroll
            for (int ii = 0; ii < 8; ii++) {
                float x0, x1;
                upk2(acc[ii][p], x0, x1);
                int i  = igrp * 8 + ii;
                int cl = cgrp * 2 + p2 * 128;
                sm[cl * 65 + i]       = x0 * rinv[ii];
                sm[(cl + 1) * 65 + i] = x1 * rinv[ii];
            }
        }
        __syncthreads();
        // coalesced writes: each row c is 64 consecutive n
#pragma unroll
        for (int k = 0; k < 8; k++) {
            int z  = t + k * 512;
            int cl = z >> 4, q4 = z & 15;
            int c  = pass * 256 + cl;
            float4 o;
            o.x = sm[cl * 65 + q4 * 4 + 0];
            o.y = sm[cl * 65 + q4 * 4 + 1];
            o.z = sm[cl * 65 + q4 * 4 + 2];
            o.w = sm[cl * 65 + q4 * 4 + 3];
            size_t g = ((size_t)b * C_CH + c) * N_SP + i0 + q4 * 4;
            float4 xv = *(const float4*)&xin[g];
            o.x += xv.x; o.y += xv.y; o.z += xv.z; o.w += xv.w;
            *(float4*)&out[g] = o;
        }
    }
}

// ---------------------------------------------------------------------------
extern "C" void kernel_launch(void* const* d_in, const int* in_sizes, int n_in,
                              void* d_out, int out_size)
{
    const float* x  = (const float*)d_in[0];
    const float* Wq = (const float*)d_in[1];
    const float* bq = (const float*)d_in[2];
    const float* Wk = (const float*)d_in[3];
    const float* bk = (const float*)d_in[4];
    const float* Wv = (const float*)d_in[5];
    const float* bv = (const float*)d_in[6];
    const float* gm = (const float*)d_in[7];
    float* out = (float*)d_out;

    void *qp, *kp, *vp;
    cudaGetSymbolAddress(&qp, g_q);
    cudaGetSymbolAddress(&kp, g_k);
    cudaGetSymbolAddress(&vp, g_v);

    proj_kernel<1><<<dim3(64, 1, 4), 256>>>(x, Wq, bq, (float*)qp, 64);
    proj_kernel<1><<<dim3(64, 1, 4), 256>>>(x, Wk, bk, (float*)kp, 64);
    proj_kernel<0><<<dim3(64, 8, 4), 256>>>(x, Wv, bv, (float*)vp, 512);

    const int SMEM = 43264 * 4;  // 173,056 B dynamic shared
    cudaFuncSetAttribute(attn_kernel, cudaFuncAttributeMaxDynamicSharedMemorySize, SMEM);
    attn_kernel<<<dim3(64, 4), 512, SMEM>>>(x, gm, out);
}

// round 2
// speedup vs baseline: 1.0017x; 1.0017x over previous
#include <cuda_runtime.h>
#include <cstdint>

#define N_SP 4096
#define C_CH 512
#define M_QK 64
#define B_SZ 4

typedef unsigned long long u64;

// Scratch (device globals, allocation-free): q,k in [B][M][N], v in [B][N][C]
__device__ float g_q[B_SZ * M_QK * N_SP];
__device__ float g_k[B_SZ * M_QK * N_SP];
__device__ float g_v[(size_t)B_SZ * N_SP * C_CH];

__device__ __forceinline__ u64 pk2(float x, float y) {
    u64 r; asm("mov.b64 %0, {%1,%2};" : "=l"(r) : "f"(x), "f"(y)); return r;
}
__device__ __forceinline__ void upk2(u64 v, float& x, float& y) {
    asm("mov.b64 {%0,%1}, %2;" : "=f"(x), "=f"(y) : "l"(v));
}
__device__ __forceinline__ u64 fma2(u64 a, u64 b, u64 c) {
    u64 d; asm("fma.rn.f32x2 %0, %1, %2, %3;" : "=l"(d) : "l"(a), "l"(b), "l"(c)); return d;
}
__device__ __forceinline__ u64 mul2(u64 a, u64 b) {
    u64 d; asm("mul.rn.f32x2 %0, %1, %2;" : "=l"(d) : "l"(a), "l"(b)); return d;
}
__device__ __forceinline__ uint32_t s2u(const void* p) {
    return (uint32_t)__cvta_generic_to_shared(p);
}
__device__ __forceinline__ void cp16(uint32_t d, const void* s) {
    asm volatile("cp.async.cg.shared.global [%0], [%1], 16;" :: "r"(d), "l"(s));
}
__device__ __forceinline__ void cp_commit() { asm volatile("cp.async.commit_group;"); }
__device__ __forceinline__ void cp_wait0()  { asm volatile("cp.async.wait_group 0;"); }

// ---------------------------------------------------------------------------
// Projection GEMM: out = W[Md,C] @ x[b][C][N] + bias
// TRANS=1: out[b][m][n] (for q,k).  TRANS=0: out[b][n][m] (for v).
// Block: 64n x 64m tile, 256 threads, micro 4n x 4m via f32x2.
// ---------------------------------------------------------------------------
template<int TRANS>
__global__ __launch_bounds__(256) void proj_kernel(
    const float* __restrict__ x, const float* __restrict__ W,
    const float* __restrict__ bias, float* __restrict__ out, int Md)
{
    __shared__ float Ws[32][66];   // [c][m], pad 66 keeps 8B alignment of pairs
    __shared__ float Xs[32][64];   // [c][n]
    int t  = threadIdx.x;
    int tx = t & 15, ty = t >> 4;
    int n0 = blockIdx.x * 64, m0 = blockIdx.y * 64, b = blockIdx.z;

    u64 acc[4][2];
#pragma unroll
    for (int i = 0; i < 4; i++)
#pragma unroll
        for (int p = 0; p < 2; p++) acc[i][p] = 0ull;

    const float* xb = x + (size_t)b * C_CH * N_SP;

    for (int cc = 0; cc < C_CH; cc += 32) {
#pragma unroll
        for (int k = 0; k < 8; k++) {
            int idx = t + k * 256;
            int m = idx >> 5, c = idx & 31;
            Ws[c][m] = W[(size_t)(m0 + m) * C_CH + cc + c];
        }
#pragma unroll
        for (int k = 0; k < 8; k++) {
            int idx = t + k * 256;
            int c = idx >> 6, n = idx & 63;
            Xs[c][n] = xb[(size_t)(cc + c) * N_SP + n0 + n];
        }
        __syncthreads();
#pragma unroll
        for (int c = 0; c < 32; c++) {
            u64 w0 = *(const u64*)&Ws[c][tx * 4];
            u64 w1 = *(const u64*)&Ws[c][tx * 4 + 2];
#pragma unroll
            for (int i = 0; i < 4; i++) {
                float xv = Xs[c][ty * 4 + i];
                u64 xd = pk2(xv, xv);
                acc[i][0] = fma2(xd, w0, acc[i][0]);
                acc[i][1] = fma2(xd, w1, acc[i][1]);
            }
        }
        __syncthreads();
    }

    float av[4][4];
#pragma unroll
    for (int i = 0; i < 4; i++) {
        upk2(acc[i][0], av[i][0], av[i][1]);
        upk2(acc[i][1], av[i][2], av[i][3]);
    }
    float bv[4];
#pragma unroll
    for (int j = 0; j < 4; j++) bv[j] = bias[m0 + tx * 4 + j];

    if (TRANS) {
        // out[b][m][n] : for each m, 4 consecutive n -> float4
#pragma unroll
        for (int j = 0; j < 4; j++) {
            float4 o;
            o.x = av[0][j] + bv[j]; o.y = av[1][j] + bv[j];
            o.z = av[2][j] + bv[j]; o.w = av[3][j] + bv[j];
            *(float4*)&out[((size_t)b * Md + m0 + tx * 4 + j) * N_SP + n0 + ty * 4] = o;
        }
    } else {
        // out[b][n][m] : for each n, 4 consecutive m -> float4
#pragma unroll
        for (int i = 0; i < 4; i++) {
            float4 o;
            o.x = av[i][0] + bv[0]; o.y = av[i][1] + bv[1];
            o.z = av[i][2] + bv[2]; o.w = av[i][3] + bv[3];
            *(float4*)&out[((size_t)b * N_SP + n0 + ty * 4 + i) * Md + m0 + tx * 4] = o;
        }
    }
}

// ---------------------------------------------------------------------------
// Fused attention: per block, 64 query positions of one batch. Online softmax
// over j-tiles of 32. Double-buffered cp.async for K/V tiles.
// acc[i][c] (64 rows x 512 cols per block) held as 32 f32x2 regs per thread.
// ---------------------------------------------------------------------------
__global__ __launch_bounds__(512, 1) void attn_kernel(
    const float* __restrict__ xin, const float* __restrict__ gamma,
    float* __restrict__ out)
{
    extern __shared__ float sm[];
    // float offsets
    const int VS  = 0;         // 2 x (32 x 512) V tiles
    const int KT  = 32768;     // 2 x (64m x 32j) K tiles
    const int QT  = 36864;     // 64m x 64i Q tile
    const int SS  = 40960;     // 64 x 33 scores / probs
    const int STM = 43072;     // running max [64]
    const int STL = 43136;     // running sum [64]
    const int STF = 43200;     // rescale factor / rinv [64]

    int t  = threadIdx.x;
    int b  = blockIdx.y;
    int i0 = blockIdx.x * 64;

    const float* qg = g_q + (size_t)b * M_QK * N_SP;
    const float* kg = g_k + (size_t)b * M_QK * N_SP;
    const float* vg = g_v + (size_t)b * N_SP * C_CH;

    if (t < 64) { sm[STM + t] = -1e30f; sm[STL + t] = 0.f; }

    uint32_t vs_u = s2u(sm + VS);
    uint32_t kt_u = s2u(sm + KT);
    uint32_t qt_u = s2u(sm + QT);

    // prologue: Q tile (transposed layout [m][i]) + j-tile 0
#pragma unroll
    for (int k = 0; k < 2; k++) {
        int z = t + k * 512;              // 1024 float4 chunks of 64x64
        int row = z >> 4, c4 = z & 15;
        cp16(qt_u + (row * 64 + c4 * 4) * 4, qg + (size_t)row * N_SP + i0 + c4 * 4);
    }
    {
        const float* vsrc = vg;           // j0 = 0, contiguous 64KB
#pragma unroll
        for (int k = 0; k < 8; k++) { int z = t + k * 512; cp16(vs_u + z * 16, vsrc + z * 4); }
        int m = t >> 3, c4 = t & 7;
        cp16(kt_u + (m * 32 + c4 * 4) * 4, kg + (size_t)m * N_SP + c4 * 4);
    }
    cp_commit();

    const int igrp = t >> 6, cgrp = t & 63;   // PV mapping
    const int i2   = t >> 4, j2   = t & 15;   // QK mapping
    const int r    = t >> 3, k8   = t & 7;    // softmax row mapping

    u64 acc[8][4];
#pragma unroll
    for (int ii = 0; ii < 8; ii++)
#pragma unroll
        for (int p = 0; p < 4; p++) acc[ii][p] = 0ull;

    const int NT = N_SP / 32;
    for (int it = 0; it < NT; ++it) {
        cp_wait0();
        __syncthreads();
        int buf = it & 1;

        if (it + 1 < NT) {
            int nb = buf ^ 1;
            int j0 = (it + 1) * 32;
            const float* vsrc = vg + (size_t)j0 * C_CH;
#pragma unroll
            for (int k = 0; k < 8; k++) {
                int z = t + k * 512;
                cp16(vs_u + (nb * 16384 + z * 4) * 4, vsrc + z * 4);
            }
            int m = t >> 3, c4 = t & 7;
            cp16(kt_u + (nb * 2048 + m * 32 + c4 * 4) * 4,
                 kg + (size_t)m * N_SP + j0 + c4 * 4);
            cp_commit();
        }

        // --- QK: each thread 2i x 2j dot products over m=64 ---
        {
            const float* KTb = sm + KT + buf * 2048;
            u64 a0 = 0ull, a1 = 0ull;
#pragma unroll
            for (int m = 0; m < 64; m++) {
                u64 k2 = *(const u64*)&KTb[m * 32 + j2 * 2];
                float2 q2 = *(const float2*)&sm[QT + m * 64 + i2 * 2];
                a0 = fma2(pk2(q2.x, q2.x), k2, a0);
                a1 = fma2(pk2(q2.y, q2.y), k2, a1);
            }
            float s00, s01, s10, s11;
            upk2(a0, s00, s01); upk2(a1, s10, s11);
            sm[SS + (i2 * 2 + 0) * 33 + j2 * 2 + 0] = s00;
            sm[SS + (i2 * 2 + 0) * 33 + j2 * 2 + 1] = s01;
            sm[SS + (i2 * 2 + 1) * 33 + j2 * 2 + 0] = s10;
            sm[SS + (i2 * 2 + 1) * 33 + j2 * 2 + 1] = s11;
        }
        __syncthreads();

        // --- online softmax row pass: 8 threads per row ---
        {
            float sv[4];
#pragma unroll
            for (int c = 0; c < 4; c++) sv[c] = sm[SS + r * 33 + k8 * 4 + c];
            float mx = fmaxf(fmaxf(sv[0], sv[1]), fmaxf(sv[2], sv[3]));
#pragma unroll
            for (int w = 1; w < 8; w <<= 1) mx = fmaxf(mx, __shfl_xor_sync(0xffffffffu, mx, w));
            float mold = sm[STM + r];
            float mnew = fmaxf(mold, mx);
            float f = __expf(mold - mnew);
            float ps = 0.f;
#pragma unroll
            for (int c = 0; c < 4; c++) {
                float p = __expf(sv[c] - mnew);
                sm[SS + r * 33 + k8 * 4 + c] = p;
                ps += p;
            }
#pragma unroll
            for (int w = 1; w < 8; w <<= 1) ps += __shfl_xor_sync(0xffffffffu, ps, w);
            if (k8 == 0) {
                sm[STL + r] = sm[STL + r] * f + ps;
                sm[STM + r] = mnew;
                sm[STF + r] = f;
            }
        }
        __syncthreads();

        // --- rescale accumulators ---
#pragma unroll
        for (int ii = 0; ii < 8; ii++) {
            float f = sm[STF + igrp * 8 + ii];
            u64 fd = pk2(f, f);
#pragma unroll
            for (int p = 0; p < 4; p++) acc[ii][p] = mul2(acc[ii][p], fd);
        }

        // --- PV: acc[i][c] += p[i][j] * v[j][c] ---
        {
            const float* VSb = sm + VS + buf * 16384;
            const float* PS  = sm + SS;
            for (int j = 0; j < 32; j++) {
                u64 v0 = *(const u64*)&VSb[j * 512 + cgrp * 2 + 0 * 128];
                u64 v1 = *(const u64*)&VSb[j * 512 + cgrp * 2 + 1 * 128];
                u64 v2 = *(const u64*)&VSb[j * 512 + cgrp * 2 + 2 * 128];
                u64 v3 = *(const u64*)&VSb[j * 512 + cgrp * 2 + 3 * 128];
#pragma unroll
                for (int ii = 0; ii < 8; ii++) {
                    float p = PS[(igrp * 8 + ii) * 33 + j];
                    u64 pd = pk2(p, p);
                    acc[ii][0] = fma2(pd, v0, acc[ii][0]);
                    acc[ii][1] = fma2(pd, v1, acc[ii][1]);
                    acc[ii][2] = fma2(pd, v2, acc[ii][2]);
                    acc[ii][3] = fma2(pd, v3, acc[ii][3]);
                }
            }
        }
    }

    // --- epilogue: out[b][c][n] = gamma * acc/l + x, smem-transposed stores ---
    __syncthreads();
    float gam = gamma[0];
    if (t < 64) sm[STF + t] = gam / sm[STL + t];
    __syncthreads();
    float rinv[8];
#pragma unroll
    for (int ii = 0; ii < 8; ii++) rinv[ii] = sm[STF + igrp * 8 + ii];

#pragma unroll
    for (int pass = 0; pass < 2; pass++) {
        if (pass) __syncthreads();
        // stage 256 c-rows x 64 i into [cl][65] buffer (aliases VS region)
#pragma unroll
        for (int p2 = 0; p2 < 2; p2++) {
            int p = pass * 2 + p2;
#pragma unroll
            for (int ii = 0; ii < 8; ii++) {
                float x0, x1;
                upk2(acc[ii][p], x0, x1);
                int i  = igrp * 8 + ii;
                int cl = cgrp * 2 + p2 * 128;
                sm[cl * 65 + i]       = x0 * rinv[ii];
                sm[(cl + 1) * 65 + i] = x1 * rinv[ii];
            }
        }
        __syncthreads();
        // coalesced writes: each row c is 64 consecutive n
#pragma unroll
        for (int k = 0; k < 8; k++) {
            int z  = t + k * 512;
            int cl = z >> 4, q4 = z & 15;
            int c  = pass * 256 + cl;
            float4 o;
            o.x = sm[cl * 65 + q4 * 4 + 0];
            o.y = sm[cl * 65 + q4 * 4 + 1];
            o.z = sm[cl * 65 + q4 * 4 + 2];
            o.w = sm[cl * 65 + q4 * 4 + 3];
            size_t g = ((size_t)b * C_CH + c) * N_SP + i0 + q4 * 4;
            float4 xv = *(const float4*)&xin[g];
            o.x += xv.x; o.y += xv.y; o.z += xv.z; o.w += xv.w;
            *(float4*)&out[g] = o;
        }
    }
}

// ---------------------------------------------------------------------------
extern "C" void kernel_launch(void* const* d_in, const int* in_sizes, int n_in,
                              void* d_out, int out_size)
{
    const float* x  = (const float*)d_in[0];
    const float* Wq = (const float*)d_in[1];
    const float* bq = (const float*)d_in[2];
    const float* Wk = (const float*)d_in[3];
    const float* bk = (const float*)d_in[4];
    const float* Wv = (const float*)d_in[5];
    const float* bv = (const float*)d_in[6];
    const float* gm = (const float*)d_in[7];
    float* out = (float*)d_out;

    void *qp, *kp, *vp;
    cudaGetSymbolAddress(&qp, g_q);
    cudaGetSymbolAddress(&kp, g_k);
    cudaGetSymbolAddress(&vp, g_v);

    proj_kernel<1><<<dim3(64, 1, 4), 256>>>(x, Wq, bq, (float*)qp, 64);
    proj_kernel<1><<<dim3(64, 1, 4), 256>>>(x, Wk, bk, (float*)kp, 64);
    proj_kernel<0><<<dim3(64, 8, 4), 256>>>(x, Wv, bv, (float*)vp, 512);

    const int SMEM = 43264 * 4;  // 173,056 B dynamic shared
    cudaFuncSetAttribute(attn_kernel, cudaFuncAttributeMaxDynamicSharedMemorySize, SMEM);
    attn_kernel<<<dim3(64, 4), 512, SMEM>>>(x, gm, out);
}

// round 4
// speedup vs baseline: 3.4024x; 3.3967x over previous
#include <cuda_runtime.h>
#include <cuda_fp16.h>
#include <cstdint>

#define N_SP 4096
#define C_CH 512
#define B_SZ 4

typedef unsigned long long u64;
typedef unsigned int u32;

// ---------------- scratch (device globals) ----------------
__device__ __half g_qh[(size_t)B_SZ * N_SP * 64];
__device__ __half g_ql[(size_t)B_SZ * N_SP * 64];
__device__ __half g_kh[(size_t)B_SZ * N_SP * 64];
__device__ __half g_kl[(size_t)B_SZ * N_SP * 64];
__device__ __half g_vh[(size_t)B_SZ * C_CH * N_SP];
__device__ float  g_S [(size_t)B_SZ * N_SP * N_SP];
__device__ __half g_P [(size_t)B_SZ * N_SP * N_SP];
__device__ float  g_l [(size_t)B_SZ * N_SP];

// ---------------- helpers ----------------
__device__ __forceinline__ u64 pk2(float x, float y) {
    u64 r; asm("mov.b64 %0, {%1,%2};" : "=l"(r) : "f"(x), "f"(y)); return r;
}
__device__ __forceinline__ void upk2(u64 v, float& x, float& y) {
    asm("mov.b64 {%0,%1}, %2;" : "=f"(x), "=f"(y) : "l"(v));
}
__device__ __forceinline__ u64 fma2(u64 a, u64 b, u64 c) {
    u64 d; asm("fma.rn.f32x2 %0, %1, %2, %3;" : "=l"(d) : "l"(a), "l"(b), "l"(c)); return d;
}
__device__ __forceinline__ u32 s2u(const void* p) { return (u32)__cvta_generic_to_shared(p); }
__device__ __forceinline__ void cp16(u32 d, const void* s) {
    asm volatile("cp.async.cg.shared.global [%0], [%1], 16;" :: "r"(d), "l"(s));
}
__device__ __forceinline__ void cp_commit() { asm volatile("cp.async.commit_group;"); }
__device__ __forceinline__ void cp_wait0()  { asm volatile("cp.async.wait_group 0;"); }
__device__ __forceinline__ void cp_wait1()  { asm volatile("cp.async.wait_group 1;"); }
__device__ __forceinline__ u32 sw128(u32 o) { return o ^ ((o >> 3) & 0x70); }

__device__ __forceinline__ void ldsm4(u32& r0, u32& r1, u32& r2, u32& r3, u32 a) {
    asm volatile("ldmatrix.sync.aligned.m8n8.x4.shared.b16 {%0,%1,%2,%3}, [%4];"
                 : "=r"(r0), "=r"(r1), "=r"(r2), "=r"(r3) : "r"(a));
}
__device__ __forceinline__ void ldsm2(u32& r0, u32& r1, u32 a) {
    asm volatile("ldmatrix.sync.aligned.m8n8.x2.shared.b16 {%0,%1}, [%2];"
                 : "=r"(r0), "=r"(r1) : "r"(a));
}
__device__ __forceinline__ void mma16816(float* d, const u32* a, const u32* b) {
    asm volatile("mma.sync.aligned.m16n8k16.row.col.f32.f16.f16.f32 "
                 "{%0,%1,%2,%3}, {%4,%5,%6,%7}, {%8,%9}, {%0,%1,%2,%3};"
                 : "+f"(d[0]), "+f"(d[1]), "+f"(d[2]), "+f"(d[3])
                 : "r"(a[0]), "r"(a[1]), "r"(a[2]), "r"(a[3]), "r"(b[0]), "r"(b[1]));
}

__device__ __forceinline__ void st_hl(__half* ph, __half* pl, size_t a,
                                      float o0, float o1, float o2, float o3) {
    __half h0 = __float2half_rn(o0), h1 = __float2half_rn(o1);
    __half h2 = __float2half_rn(o2), h3 = __float2half_rn(o3);
    __half l0 = __float2half_rn(o0 - __half2float(h0));
    __half l1 = __float2half_rn(o1 - __half2float(h1));
    __half l2 = __float2half_rn(o2 - __half2float(h2));
    __half l3 = __float2half_rn(o3 - __half2float(h3));
    *(__half2*)(ph + a)     = __halves2half2(h0, h1);
    *(__half2*)(ph + a + 2) = __halves2half2(h2, h3);
    *(__half2*)(pl + a)     = __halves2half2(l0, l1);
    *(__half2*)(pl + a + 2) = __halves2half2(l2, l3);
}

// ---------------------------------------------------------------------------
// Projection: W[Md,C] @ x[b][C][N] + bias.
// TRANS=0: q/k -> [b][n][Md] fp16 hi/lo.  TRANS=1: v -> [b][c][n] fp16.
// ---------------------------------------------------------------------------
template<int TRANS>
__global__ __launch_bounds__(256) void proj_kernel(
    const float* __restrict__ x, const float* __restrict__ W,
    const float* __restrict__ bias, __half* __restrict__ oh,
    __half* __restrict__ ol, int Md)
{
    __shared__ float Ws[32][66];
    __shared__ float Xs[32][64];
    int t = threadIdx.x;
    int tx = t & 15, ty = t >> 4;
    int n0 = blockIdx.x * 64, m0 = blockIdx.y * 64, b = blockIdx.z;

    u64 acc[4][2];
#pragma unroll
    for (int i = 0; i < 4; i++) { acc[i][0] = 0ull; acc[i][1] = 0ull; }

    const float* xb = x + (size_t)b * C_CH * N_SP;
    for (int cc = 0; cc < C_CH; cc += 32) {
#pragma unroll
        for (int k = 0; k < 8; k++) {
            int idx = t + k * 256, m = idx >> 5, c = idx & 31;
            Ws[c][m] = W[(size_t)(m0 + m) * C_CH + cc + c];
        }
#pragma unroll
        for (int k = 0; k < 8; k++) {
            int idx = t + k * 256, c = idx >> 6, n = idx & 63;
            Xs[c][n] = xb[(size_t)(cc + c) * N_SP + n0 + n];
        }
        __syncthreads();
#pragma unroll
        for (int c = 0; c < 32; c++) {
            u64 w0 = *(const u64*)&Ws[c][tx * 4];
            u64 w1 = *(const u64*)&Ws[c][tx * 4 + 2];
#pragma unroll
            for (int i = 0; i < 4; i++) {
                float xv = Xs[c][ty * 4 + i];
                u64 xd = pk2(xv, xv);
                acc[i][0] = fma2(xd, w0, acc[i][0]);
                acc[i][1] = fma2(xd, w1, acc[i][1]);
            }
        }
        __syncthreads();
    }

    float av[4][4];
#pragma unroll
    for (int i = 0; i < 4; i++) { upk2(acc[i][0], av[i][0], av[i][1]); upk2(acc[i][1], av[i][2], av[i][3]); }
    float bv[4];
#pragma unroll
    for (int j = 0; j < 4; j++) bv[j] = bias[m0 + tx * 4 + j];

    if (TRANS == 0) {
#pragma unroll
        for (int i = 0; i < 4; i++) {
            size_t a = ((size_t)b * N_SP + n0 + ty * 4 + i) * Md + m0 + tx * 4;
            st_hl(oh, ol, a, av[i][0] + bv[0], av[i][1] + bv[1], av[i][2] + bv[2], av[i][3] + bv[3]);
        }
    } else {
#pragma unroll
        for (int j = 0; j < 4; j++) {
            size_t a = ((size_t)b * Md + m0 + tx * 4 + j) * N_SP + n0 + ty * 4;
            float o0 = av[0][j] + bv[j], o1 = av[1][j] + bv[j];
            float o2 = av[2][j] + bv[j], o3 = av[3][j] + bv[j];
            *(__half2*)(oh + a)     = __halves2half2(__float2half_rn(o0), __float2half_rn(o1));
            *(__half2*)(oh + a + 2) = __halves2half2(__float2half_rn(o2), __float2half_rn(o3));
        }
    }
}

// ---------------------------------------------------------------------------
// S-GEMM: S[b][i][j] = q·k^T via 3-term hi/lo HMMA. CTA: 128i x 128j.
// 8 warps: wi=wid&1 (64 i), wj=wid>>1 (32 j).
// ---------------------------------------------------------------------------
__global__ __launch_bounds__(256, 2) void sgemm_kernel()
{
    extern __shared__ char smx[];
    const u32 QH = 0, QL = 16384, KH = 32768, KL = 49152;
    u32 sb = s2u(smx);
    int t = threadIdx.x, wid = t >> 5, l = t & 31;
    int j0 = blockIdx.x * 128, i0 = blockIdx.y * 128, b = blockIdx.z;

    const char* qhp = (const char*)(g_qh + ((size_t)b * N_SP + i0) * 64);
    const char* qlp = (const char*)(g_ql + ((size_t)b * N_SP + i0) * 64);
    const char* khp = (const char*)(g_kh + ((size_t)b * N_SP + j0) * 64);
    const char* klp = (const char*)(g_kl + ((size_t)b * N_SP + j0) * 64);

#pragma unroll
    for (int it = 0; it < 4; it++) {
        int z = t + it * 256, r = z >> 3, c = z & 7;
        u32 off = sw128(r * 128 + c * 16);
        int go = r * 128 + c * 16;
        cp16(sb + QH + off, qhp + go);
        cp16(sb + QL + off, qlp + go);
        cp16(sb + KH + off, khp + go);
        cp16(sb + KL + off, klp + go);
    }
    cp_commit(); cp_wait0();
    __syncthreads();

    int wi = wid & 1, wj = wid >> 1;
    int g = l >> 2, t4 = l & 3;

    float acc[4][4][4];
#pragma unroll
    for (int i = 0; i < 4; i++)
#pragma unroll
        for (int j = 0; j < 4; j++)
#pragma unroll
            for (int p = 0; p < 4; p++) acc[i][j][p] = 0.f;

    const u32 ab[3] = { QH, QH, QL };
    const u32 bb[3] = { KH, KL, KH };

#pragma unroll
    for (int term = 0; term < 3; term++) {
#pragma unroll
        for (int ks = 0; ks < 4; ks++) {
            u32 af[4][4], bf[4][2];
#pragma unroll
            for (int ifr = 0; ifr < 4; ifr++) {
                u32 a = sb + ab[term] + sw128((wi * 64 + ifr * 16 + (l & 15)) * 128
                                              + ks * 32 + ((l >> 4) & 1) * 16);
                ldsm4(af[ifr][0], af[ifr][1], af[ifr][2], af[ifr][3], a);
            }
#pragma unroll
            for (int jfr = 0; jfr < 4; jfr++) {
                u32 a = sb + bb[term] + sw128((wj * 32 + jfr * 8 + (l & 7)) * 128
                                              + ks * 32 + ((l >> 3) & 1) * 16);
                ldsm2(bf[jfr][0], bf[jfr][1], a);
            }
#pragma unroll
            for (int ifr = 0; ifr < 4; ifr++)
#pragma unroll
                for (int jfr = 0; jfr < 4; jfr++)
                    mma16816(acc[ifr][jfr], af[ifr], bf[jfr]);
        }
    }

    float* S = g_S + (size_t)b * N_SP * N_SP;
#pragma unroll
    for (int ifr = 0; ifr < 4; ifr++) {
        int r0 = i0 + wi * 64 + ifr * 16 + g;
#pragma unroll
        for (int jfr = 0; jfr < 4; jfr++) {
            int col = j0 + wj * 32 + jfr * 8 + t4 * 2;
            float2 d0 = { acc[ifr][jfr][0], acc[ifr][jfr][1] };
            float2 d1 = { acc[ifr][jfr][2], acc[ifr][jfr][3] };
            *(float2*)&S[(size_t)r0 * N_SP + col]       = d0;
            *(float2*)&S[(size_t)(r0 + 8) * N_SP + col] = d1;
        }
    }
}

// ---------------------------------------------------------------------------
// Softmax: one row per block. P = fp16(exp(s - max)); l = sum of fp16 values.
// ---------------------------------------------------------------------------
__global__ __launch_bounds__(256) void softmax_kernel()
{
    __shared__ float red[8];
    int i = blockIdx.x, b = blockIdx.y, t = threadIdx.x, wid = t >> 5;
    const float* S = g_S + ((size_t)b * N_SP + i) * N_SP;
    __half* P = g_P + ((size_t)b * N_SP + i) * N_SP;

    float4 v[4];
    float mx = -1e30f;
#pragma unroll
    for (int k = 0; k < 4; k++) {
        v[k] = *(const float4*)&S[(k * 256 + t) * 4];
        mx = fmaxf(mx, fmaxf(fmaxf(v[k].x, v[k].y), fmaxf(v[k].z, v[k].w)));
    }
#pragma unroll
    for (int w = 1; w < 32; w <<= 1) mx = fmaxf(mx, __shfl_xor_sync(~0u, mx, w));
    if ((t & 31) == 0) red[wid] = mx;
    __syncthreads();
    mx = red[0];
#pragma unroll
    for (int w = 1; w < 8; w++) mx = fmaxf(mx, red[w]);
    __syncthreads();

    float sum = 0.f;
#pragma unroll
    for (int k = 0; k < 4; k++) {
        __half h0 = __float2half_rn(__expf(v[k].x - mx));
        __half h1 = __float2half_rn(__expf(v[k].y - mx));
        __half h2 = __float2half_rn(__expf(v[k].z - mx));
        __half h3 = __float2half_rn(__expf(v[k].w - mx));
        sum += __half2float(h0) + __half2float(h1) + __half2float(h2) + __half2float(h3);
        *(__half2*)&P[(k * 256 + t) * 4]     = __halves2half2(h0, h1);
        *(__half2*)&P[(k * 256 + t) * 4 + 2] = __halves2half2(h2, h3);
    }
#pragma unroll
    for (int w = 1; w < 32; w <<= 1) sum += __shfl_xor_sync(~0u, sum, w);
    if ((t & 31) == 0) red[wid] = sum;
    __syncthreads();
    if (t == 0) {
        float s = 0.f;
#pragma unroll
        for (int w = 0; w < 8; w++) s += red[w];
        g_l[(size_t)b * N_SP + i] = s;
    }
}

// ---------------------------------------------------------------------------
// PV: feat[i][c] = sum_j P[i][j] V[c][j]. CTA: 128i x 128c, j-chunks of 64,
// double-buffered cp.async. Epilogue: out = gamma*feat/l + x.
// ---------------------------------------------------------------------------
__global__ __launch_bounds__(256, 2) void pv_kernel(
    const float* __restrict__ xin, const float* __restrict__ gamma,
    float* __restrict__ out)
{
    extern __shared__ char smx[];
    const u32 PT = 0, VT = 32768;   // each: 2 buffers x 16 KB
    u32 sb = s2u(smx);
    int t = threadIdx.x, wid = t >> 5, l = t & 31;
    int c0 = blockIdx.x * 128, i0 = blockIdx.y * 128, b = blockIdx.z;

    const char* pp = (const char*)(g_P  + ((size_t)b * N_SP + i0) * N_SP);
    const char* vp = (const char*)(g_vh + ((size_t)b * C_CH + c0) * N_SP);

    auto load_chunk = [&](int jc, int s) {
        size_t jb = (size_t)jc * 128;
#pragma unroll
        for (int it = 0; it < 4; it++) {
            int z = t + it * 256, r = z >> 3, c = z & 7;
            u32 off = s * 16384 + sw128(r * 128 + c * 16);
            cp16(sb + PT + off, pp + (size_t)r * 8192 + jb + c * 16);
            cp16(sb + VT + off, vp + (size_t)r * 8192 + jb + c * 16);
        }
        cp_commit();
    };

    int wi = wid & 1, wc = wid >> 1;
    int g = l >> 2, t4 = l & 3;

    float acc[4][4][4];
#pragma unroll
    for (int i = 0; i < 4; i++)
#pragma unroll
        for (int j = 0; j < 4; j++)
#pragma unroll
            for (int p = 0; p < 4; p++) acc[i][j][p] = 0.f;

    load_chunk(0, 0);
    for (int it = 0; it < 64; it++) {
        int s = it & 1;
        if (it + 1 < 64) { load_chunk(it + 1, s ^ 1); cp_wait1(); }
        else cp_wait0();
        __syncthreads();
#pragma unroll
        for (int ks = 0; ks < 4; ks++) {
            u32 af[4][4], bf[4][2];
#pragma unroll
            for (int ifr = 0; ifr < 4; ifr++) {
                u32 a = sb + PT + s * 16384 + sw128((wi * 64 + ifr * 16 + (l & 15)) * 128
                                                    + ks * 32 + ((l >> 4) & 1) * 16);
                ldsm4(af[ifr][0], af[ifr][1], af[ifr][2], af[ifr][3], a);
            }
#pragma unroll
            for (int cfr = 0; cfr < 4; cfr++) {
                u32 a = sb + VT + s * 16384 + sw128((wc * 32 + cfr * 8 + (l & 7)) * 128
                                                    + ks * 32 + ((l >> 3) & 1) * 16);
                ldsm2(bf[cfr][0], bf[cfr][1], a);
            }
#pragma unroll
            for (int ifr = 0; ifr < 4; ifr++)
#pragma unroll
                for (int cfr = 0; cfr < 4; cfr++)
                    mma16816(acc[ifr][cfr], af[ifr], bf[cfr]);
        }
        __syncthreads();
    }

    float gam = gamma[0];
    float linv[4][2];
#pragma unroll
    for (int ifr = 0; ifr < 4; ifr++) {
        int i = i0 + wi * 64 + ifr * 16 + g;
        linv[ifr][0] = gam / g_l[(size_t)b * N_SP + i];
        linv[ifr][1] = gam / g_l[(size_t)b * N_SP + i + 8];
    }
#pragma unroll
    for (int ifr = 0; ifr < 4; ifr++) {
        int i = i0 + wi * 64 + ifr * 16 + g;
#pragma unroll
        for (int cfr = 0; cfr < 4; cfr++) {
            int c = c0 + wc * 32 + cfr * 8 + t4 * 2;
            size_t base = ((size_t)b * C_CH + c) * N_SP;
            out[base + i]            = acc[ifr][cfr][0] * linv[ifr][0] + xin[base + i];
            out[base + N_SP + i]     = acc[ifr][cfr][1] * linv[ifr][0] + xin[base + N_SP + i];
            out[base + i + 8]        = acc[ifr][cfr][2] * linv[ifr][1] + xin[base + i + 8];
            out[base + N_SP + i + 8] = acc[ifr][cfr][3] * linv[ifr][1] + xin[base + N_SP + i + 8];
        }
    }
}

// ---------------------------------------------------------------------------
extern "C" void kernel_launch(void* const* d_in, const int* in_sizes, int n_in,
                              void* d_out, int out_size)
{
    const float* x  = (const float*)d_in[0];
    const float* Wq = (const float*)d_in[1];
    const float* bq = (const float*)d_in[2];
    const float* Wk = (const float*)d_in[3];
    const float* bk = (const float*)d_in[4];
    const float* Wv = (const float*)d_in[5];
    const float* bv = (const float*)d_in[6];
    const float* gm = (const float*)d_in[7];
    float* out = (float*)d_out;

    void *qh, *ql, *kh, *kl, *vh;
    cudaGetSymbolAddress(&qh, g_qh); cudaGetSymbolAddress(&ql, g_ql);
    cudaGetSymbolAddress(&kh, g_kh); cudaGetSymbolAddress(&kl, g_kl);
    cudaGetSymbolAddress(&vh, g_vh);

    proj_kernel<0><<<dim3(64, 1, 4), 256>>>(x, Wq, bq, (__half*)qh, (__half*)ql, 64);
    proj_kernel<0><<<dim3(64, 1, 4), 256>>>(x, Wk, bk, (__half*)kh, (__half*)kl, 64);
    proj_kernel<1><<<dim3(64, 8, 4), 256>>>(x, Wv, bv, (__half*)vh, nullptr, 512);

    cudaFuncSetAttribute(sgemm_kernel, cudaFuncAttributeMaxDynamicSharedMemorySize, 65536);
    sgemm_kernel<<<dim3(32, 32, 4), 256, 65536>>>();

    softmax_kernel<<<dim3(4096, 4), 256>>>();

    cudaFuncSetAttribute(pv_kernel, cudaFuncAttributeMaxDynamicSharedMemorySize, 65536);
    pv_kernel<<<dim3(4, 32, 4), 256, 65536>>>(x, gm, out);
}

// round 5
// speedup vs baseline: 6.0840x; 1.7881x over previous
#include <cuda_runtime.h>
#include <cuda_fp16.h>
#include <cstdint>

#define N_SP 4096
#define C_CH 512
#define B_SZ 4

typedef unsigned long long u64;
typedef unsigned int u32;

// ---------------- scratch (device globals) ----------------
__device__ __half g_xth[(size_t)B_SZ * N_SP * C_CH];   // x^T hi  [b][n][c]
__device__ __half g_xtl[(size_t)B_SZ * N_SP * C_CH];   // x^T lo
__device__ __half g_wqh[64 * C_CH], g_wql[64 * C_CH];
__device__ __half g_wkh[64 * C_CH], g_wkl[64 * C_CH];
__device__ __half g_wvh[C_CH * C_CH], g_wvl[C_CH * C_CH];
__device__ __half g_qh[(size_t)B_SZ * N_SP * 64];
__device__ __half g_ql[(size_t)B_SZ * N_SP * 64];
__device__ __half g_kh[(size_t)B_SZ * N_SP * 64];
__device__ __half g_kl[(size_t)B_SZ * N_SP * 64];
__device__ __half g_vh[(size_t)B_SZ * C_CH * N_SP];
__device__ float  g_S [(size_t)B_SZ * N_SP * N_SP];
__device__ __half g_P [(size_t)B_SZ * N_SP * N_SP];
__device__ float  g_l [(size_t)B_SZ * N_SP];

// ---------------- helpers ----------------
__device__ __forceinline__ u32 s2u(const void* p) { return (u32)__cvta_generic_to_shared(p); }
__device__ __forceinline__ void cp16(u32 d, const void* s) {
    asm volatile("cp.async.cg.shared.global [%0], [%1], 16;" :: "r"(d), "l"(s));
}
__device__ __forceinline__ void cp_commit() { asm volatile("cp.async.commit_group;"); }
__device__ __forceinline__ void cp_wait0()  { asm volatile("cp.async.wait_group 0;"); }
__device__ __forceinline__ void cp_wait1()  { asm volatile("cp.async.wait_group 1;"); }
__device__ __forceinline__ u32 sw128(u32 o) { return o ^ ((o >> 3) & 0x70); }

__device__ __forceinline__ void ldsm4(u32& r0, u32& r1, u32& r2, u32& r3, u32 a) {
    asm volatile("ldmatrix.sync.aligned.m8n8.x4.shared.b16 {%0,%1,%2,%3}, [%4];"
                 : "=r"(r0), "=r"(r1), "=r"(r2), "=r"(r3) : "r"(a));
}
__device__ __forceinline__ void ldsm2(u32& r0, u32& r1, u32 a) {
    asm volatile("ldmatrix.sync.aligned.m8n8.x2.shared.b16 {%0,%1}, [%2];"
                 : "=r"(r0), "=r"(r1) : "r"(a));
}
__device__ __forceinline__ void mma16816(float* d, const u32* a, const u32* b) {
    asm volatile("mma.sync.aligned.m16n8k16.row.col.f32.f16.f16.f32 "
                 "{%0,%1,%2,%3}, {%4,%5,%6,%7}, {%8,%9}, {%0,%1,%2,%3};"
                 : "+f"(d[0]), "+f"(d[1]), "+f"(d[2]), "+f"(d[3])
                 : "r"(a[0]), "r"(a[1]), "r"(a[2]), "r"(a[3]), "r"(b[0]), "r"(b[1]));
}

__device__ __forceinline__ void st_hl2(__half* ph, __half* pl, size_t a, float o0, float o1) {
    __half h0 = __float2half_rn(o0), h1 = __float2half_rn(o1);
    __half l0 = __float2half_rn(o0 - __half2float(h0));
    __half l1 = __float2half_rn(o1 - __half2float(h1));
    *(__half2*)(ph + a) = __halves2half2(h0, h1);
    *(__half2*)(pl + a) = __halves2half2(l0, l1);
}

// ---------------------------------------------------------------------------
// xconv: x [b][C][N] fp32 -> x^T [b][n][C] fp16 hi/lo (32x32 smem transpose)
// ---------------------------------------------------------------------------
__global__ __launch_bounds__(256) void xconv_kernel(const float* __restrict__ x)
{
    __shared__ float tile[32][33];
    int tx = threadIdx.x & 31, ty = threadIdx.x >> 5;
    int n0 = blockIdx.x * 32, c0 = blockIdx.y * 32, b = blockIdx.z;
#pragma unroll
    for (int k = 0; k < 4; k++)
        tile[ty + k * 8][tx] = x[((size_t)b * C_CH + c0 + ty + k * 8) * N_SP + n0 + tx];
    __syncthreads();
#pragma unroll
    for (int k = 0; k < 4; k++) {
        int n = ty + k * 8;
        float v = tile[tx][n];
        __half h = __float2half_rn(v);
        size_t a = ((size_t)b * N_SP + n0 + n) * C_CH + c0 + tx;
        g_xth[a] = h;
        g_xtl[a] = __float2half_rn(v - __half2float(h));
    }
}

// ---------------------------------------------------------------------------
// wconv: fp32 weights -> fp16 hi/lo
// ---------------------------------------------------------------------------
__global__ __launch_bounds__(256) void wconv_kernel(
    const float* __restrict__ w, __half* __restrict__ wh, __half* __restrict__ wl, int n)
{
    int i = blockIdx.x * 256 + threadIdx.x;
    if (i < n) {
        float v = w[i];
        __half h = __float2half_rn(v);
        wh[i] = h;
        wl[i] = __float2half_rn(v - __half2float(h));
    }
}

// ---------------------------------------------------------------------------
// projqk: q/k[n][64] = x^T @ W^T + bias (3-term hi/lo HMMA), out split hi/lo.
// CTA: 128n x 64m. blockIdx.y: 0 = q, 1 = k.
// ---------------------------------------------------------------------------
__global__ __launch_bounds__(256) void projqk_kernel(
    const float* __restrict__ bq, const float* __restrict__ bk)
{
    extern __shared__ char smx[];
    // per buffer (stride 49152): XH 0 | XL 16384 | WH 32768 | WL 40960
    u32 sb = s2u(smx);
    int t = threadIdx.x, wid = t >> 5, l = t & 31;
    int n0 = blockIdx.x * 128, which = blockIdx.y, b = blockIdx.z;

    const char* xh = (const char*)(g_xth + ((size_t)b * N_SP + n0) * C_CH);
    const char* xl = (const char*)(g_xtl + ((size_t)b * N_SP + n0) * C_CH);
    const char* wh = (const char*)(which ? g_wkh : g_wqh);
    const char* wl = (const char*)(which ? g_wkl : g_wql);
    const float* bias = which ? bk : bq;
    __half* oh = (which ? g_kh : g_qh) + ((size_t)b * N_SP + n0) * 64;
    __half* ol = (which ? g_kl : g_ql) + ((size_t)b * N_SP + n0) * 64;

    auto load = [&](int kc, int s) {
        u32 base = s * 49152;
#pragma unroll
        for (int k2 = 0; k2 < 4; k2++) {
            int z = t + k2 * 256, r = z >> 3, c = z & 7;
            u32 off = sw128(r * 128 + c * 16);
            size_t go = (size_t)r * 1024 + kc * 128 + c * 16;
            cp16(sb + base + off, xh + go);
            cp16(sb + base + 16384 + off, xl + go);
        }
#pragma unroll
        for (int k2 = 0; k2 < 2; k2++) {
            int z = t + k2 * 256, r = z >> 3, c = z & 7;
            u32 off = sw128(r * 128 + c * 16);
            size_t go = (size_t)r * 1024 + kc * 128 + c * 16;
            cp16(sb + base + 32768 + off, wh + go);
            cp16(sb + base + 40960 + off, wl + go);
        }
        cp_commit();
    };

    int wn = wid & 3, wm = wid >> 2;
    float acc[2][4][4];
#pragma unroll
    for (int i = 0; i < 2; i++)
#pragma unroll
        for (int j = 0; j < 4; j++)
#pragma unroll
            for (int p = 0; p < 4; p++) acc[i][j][p] = 0.f;

    load(0, 0);
    for (int kc = 0; kc < 8; kc++) {
        int s = kc & 1;
        if (kc + 1 < 8) { load(kc + 1, s ^ 1); cp_wait1(); }
        else cp_wait0();
        __syncthreads();
        u32 xb0 = sb + s * 49152, wb0 = xb0 + 32768;
#pragma unroll
        for (int ks = 0; ks < 4; ks++) {
            u32 ah[2][4], al[2][4], bh[4][2], bl[4][2];
#pragma unroll
            for (int ifr = 0; ifr < 2; ifr++) {
                u32 ro = (wn * 32 + ifr * 16 + (l & 15)) * 128 + ks * 32 + ((l >> 4) & 1) * 16;
                ldsm4(ah[ifr][0], ah[ifr][1], ah[ifr][2], ah[ifr][3], xb0 + sw128(ro));
                ldsm4(al[ifr][0], al[ifr][1], al[ifr][2], al[ifr][3], xb0 + 16384 + sw128(ro));
            }
#pragma unroll
            for (int jfr = 0; jfr < 4; jfr++) {
                u32 ro = (wm * 32 + jfr * 8 + (l & 7)) * 128 + ks * 32 + ((l >> 3) & 1) * 16;
                ldsm2(bh[jfr][0], bh[jfr][1], wb0 + sw128(ro));
                ldsm2(bl[jfr][0], bl[jfr][1], wb0 + 8192 + sw128(ro));
            }
#pragma unroll
            for (int ifr = 0; ifr < 2; ifr++)
#pragma unroll
                for (int jfr = 0; jfr < 4; jfr++) {
                    mma16816(acc[ifr][jfr], ah[ifr], bh[jfr]);
                    mma16816(acc[ifr][jfr], ah[ifr], bl[jfr]);
                    mma16816(acc[ifr][jfr], al[ifr], bh[jfr]);
                }
        }
        __syncthreads();
    }

    int g = l >> 2, t4 = l & 3;
#pragma unroll
    for (int ifr = 0; ifr < 2; ifr++) {
        int r0 = wn * 32 + ifr * 16 + g;
#pragma unroll
        for (int jfr = 0; jfr < 4; jfr++) {
            int m = wm * 32 + jfr * 8 + t4 * 2;
            float bv0 = bias[m], bv1 = bias[m + 1];
            st_hl2(oh, ol, (size_t)r0 * 64 + m,
                   acc[ifr][jfr][0] + bv0, acc[ifr][jfr][1] + bv1);
            st_hl2(oh, ol, (size_t)(r0 + 8) * 64 + m,
                   acc[ifr][jfr][2] + bv0, acc[ifr][jfr][3] + bv1);
        }
    }
}

// ---------------------------------------------------------------------------
// projv: v[c][n] = Wv @ x + bias (single-term fp16 HMMA). CTA: 128c x 128n.
// ---------------------------------------------------------------------------
__global__ __launch_bounds__(256) void projv_kernel(const float* __restrict__ bv)
{
    extern __shared__ char smx[];
    // per buffer (stride 32768): A(Wv) 0 | B(x) 16384
    u32 sb = s2u(smx);
    int t = threadIdx.x, wid = t >> 5, l = t & 31;
    int n0 = blockIdx.x * 128, c0 = blockIdx.y * 128, b = blockIdx.z;

    const char* ap = (const char*)(g_wvh + (size_t)c0 * C_CH);
    const char* bp = (const char*)(g_xth + ((size_t)b * N_SP + n0) * C_CH);
    __half* vo = g_vh + ((size_t)b * C_CH + c0) * N_SP;

    auto load = [&](int kc, int s) {
        u32 base = s * 32768;
#pragma unroll
        for (int k2 = 0; k2 < 4; k2++) {
            int z = t + k2 * 256, r = z >> 3, c = z & 7;
            u32 off = sw128(r * 128 + c * 16);
            size_t go = (size_t)r * 1024 + kc * 128 + c * 16;
            cp16(sb + base + off, ap + go);
            cp16(sb + base + 16384 + off, bp + go);
        }
        cp_commit();
    };

    int wi = wid & 1, wj = wid >> 1;
    float acc[4][4][4];
#pragma unroll
    for (int i = 0; i < 4; i++)
#pragma unroll
        for (int j = 0; j < 4; j++)
#pragma unroll
            for (int p = 0; p < 4; p++) acc[i][j][p] = 0.f;

    load(0, 0);
    for (int kc = 0; kc < 8; kc++) {
        int s = kc & 1;
        if (kc + 1 < 8) { load(kc + 1, s ^ 1); cp_wait1(); }
        else cp_wait0();
        __syncthreads();
        u32 ab0 = sb + s * 32768, bb0 = ab0 + 16384;
#pragma unroll
        for (int ks = 0; ks < 4; ks++) {
            u32 af[4][4], bf[4][2];
#pragma unroll
            for (int ifr = 0; ifr < 4; ifr++) {
                u32 ro = (wi * 64 + ifr * 16 + (l & 15)) * 128 + ks * 32 + ((l >> 4) & 1) * 16;
                ldsm4(af[ifr][0], af[ifr][1], af[ifr][2], af[ifr][3], ab0 + sw128(ro));
            }
#pragma unroll
            for (int jfr = 0; jfr < 4; jfr++) {
                u32 ro = (wj * 32 + jfr * 8 + (l & 7)) * 128 + ks * 32 + ((l >> 3) & 1) * 16;
                ldsm2(bf[jfr][0], bf[jfr][1], bb0 + sw128(ro));
            }
#pragma unroll
            for (int ifr = 0; ifr < 4; ifr++)
#pragma unroll
                for (int jfr = 0; jfr < 4; jfr++)
                    mma16816(acc[ifr][jfr], af[ifr], bf[jfr]);
        }
        __syncthreads();
    }

    int g = l >> 2, t4 = l & 3;
#pragma unroll
    for (int ifr = 0; ifr < 4; ifr++) {
        int cl = wi * 64 + ifr * 16 + g;
        float b0 = bv[c0 + cl], b1 = bv[c0 + cl + 8];
#pragma unroll
        for (int jfr = 0; jfr < 4; jfr++) {
            int nl = n0 + wj * 32 + jfr * 8 + t4 * 2;
            *(__half2*)(vo + (size_t)cl * N_SP + nl) =
                __halves2half2(__float2half_rn(acc[ifr][jfr][0] + b0),
                               __float2half_rn(acc[ifr][jfr][1] + b0));
            *(__half2*)(vo + (size_t)(cl + 8) * N_SP + nl) =
                __halves2half2(__float2half_rn(acc[ifr][jfr][2] + b1),
                               __float2half_rn(acc[ifr][jfr][3] + b1));
        }
    }
}

// ---------------------------------------------------------------------------
// S-GEMM: S = q.k^T via 3-term hi/lo HMMA. CTA: 128i x 128j.
// ---------------------------------------------------------------------------
__global__ __launch_bounds__(256, 2) void sgemm_kernel()
{
    extern __shared__ char smx[];
    const u32 QH = 0, QL = 16384, KH = 32768, KL = 49152;
    u32 sb = s2u(smx);
    int t = threadIdx.x, wid = t >> 5, l = t & 31;
    int j0 = blockIdx.x * 128, i0 = blockIdx.y * 128, b = blockIdx.z;

    const char* qhp = (const char*)(g_qh + ((size_t)b * N_SP + i0) * 64);
    const char* qlp = (const char*)(g_ql + ((size_t)b * N_SP + i0) * 64);
    const char* khp = (const char*)(g_kh + ((size_t)b * N_SP + j0) * 64);
    const char* klp = (const char*)(g_kl + ((size_t)b * N_SP + j0) * 64);

#pragma unroll
    for (int it = 0; it < 4; it++) {
        int z = t + it * 256, r = z >> 3, c = z & 7;
        u32 off = sw128(r * 128 + c * 16);
        int go = r * 128 + c * 16;
        cp16(sb + QH + off, qhp + go);
        cp16(sb + QL + off, qlp + go);
        cp16(sb + KH + off, khp + go);
        cp16(sb + KL + off, klp + go);
    }
    cp_commit(); cp_wait0();
    __syncthreads();

    int wi = wid & 1, wj = wid >> 1;
    int g = l >> 2, t4 = l & 3;

    float acc[4][4][4];
#pragma unroll
    for (int i = 0; i < 4; i++)
#pragma unroll
        for (int j = 0; j < 4; j++)
#pragma unroll
            for (int p = 0; p < 4; p++) acc[i][j][p] = 0.f;

    const u32 ab[3] = { QH, QH, QL };
    const u32 bb[3] = { KH, KL, KH };

#pragma unroll
    for (int term = 0; term < 3; term++) {
#pragma unroll
        for (int ks = 0; ks < 4; ks++) {
            u32 af[4][4], bf[4][2];
#pragma unroll
            for (int ifr = 0; ifr < 4; ifr++) {
                u32 a = sb + ab[term] + sw128((wi * 64 + ifr * 16 + (l & 15)) * 128
                                              + ks * 32 + ((l >> 4) & 1) * 16);
                ldsm4(af[ifr][0], af[ifr][1], af[ifr][2], af[ifr][3], a);
            }
#pragma unroll
            for (int jfr = 0; jfr < 4; jfr++) {
                u32 a = sb + bb[term] + sw128((wj * 32 + jfr * 8 + (l & 7)) * 128
                                              + ks * 32 + ((l >> 3) & 1) * 16);
                ldsm2(bf[jfr][0], bf[jfr][1], a);
            }
#pragma unroll
            for (int ifr = 0; ifr < 4; ifr++)
#pragma unroll
                for (int jfr = 0; jfr < 4; jfr++)
                    mma16816(acc[ifr][jfr], af[ifr], bf[jfr]);
        }
    }

    float* S = g_S + (size_t)b * N_SP * N_SP;
#pragma unroll
    for (int ifr = 0; ifr < 4; ifr++) {
        int r0 = i0 + wi * 64 + ifr * 16 + g;
#pragma unroll
        for (int jfr = 0; jfr < 4; jfr++) {
            int col = j0 + wj * 32 + jfr * 8 + t4 * 2;
            float2 d0 = { acc[ifr][jfr][0], acc[ifr][jfr][1] };
            float2 d1 = { acc[ifr][jfr][2], acc[ifr][jfr][3] };
            *(float2*)&S[(size_t)r0 * N_SP + col]       = d0;
            *(float2*)&S[(size_t)(r0 + 8) * N_SP + col] = d1;
        }
    }
}

// ---------------------------------------------------------------------------
// Softmax: one row per block. P = fp16(exp(s - max)); l = sum of fp16 values.
// ---------------------------------------------------------------------------
__global__ __launch_bounds__(256) void softmax_kernel()
{
    __shared__ float red[8];
    int i = blockIdx.x, b = blockIdx.y, t = threadIdx.x, wid = t >> 5;
    const float* S = g_S + ((size_t)b * N_SP + i) * N_SP;
    __half* P = g_P + ((size_t)b * N_SP + i) * N_SP;

    float4 v[4];
    float mx = -1e30f;
#pragma unroll
    for (int k = 0; k < 4; k++) {
        v[k] = *(const float4*)&S[(k * 256 + t) * 4];
        mx = fmaxf(mx, fmaxf(fmaxf(v[k].x, v[k].y), fmaxf(v[k].z, v[k].w)));
    }
#pragma unroll
    for (int w = 1; w < 32; w <<= 1) mx = fmaxf(mx, __shfl_xor_sync(~0u, mx, w));
    if ((t & 31) == 0) red[wid] = mx;
    __syncthreads();
    mx = red[0];
#pragma unroll
    for (int w = 1; w < 8; w++) mx = fmaxf(mx, red[w]);
    __syncthreads();

    float sum = 0.f;
#pragma unroll
    for (int k = 0; k < 4; k++) {
        __half h0 = __float2half_rn(__expf(v[k].x - mx));
        __half h1 = __float2half_rn(__expf(v[k].y - mx));
        __half h2 = __float2half_rn(__expf(v[k].z - mx));
        __half h3 = __float2half_rn(__expf(v[k].w - mx));
        sum += __half2float(h0) + __half2float(h1) + __half2float(h2) + __half2float(h3);
        *(__half2*)&P[(k * 256 + t) * 4]     = __halves2half2(h0, h1);
        *(__half2*)&P[(k * 256 + t) * 4 + 2] = __halves2half2(h2, h3);
    }
#pragma unroll
    for (int w = 1; w < 32; w <<= 1) sum += __shfl_xor_sync(~0u, sum, w);
    if ((t & 31) == 0) red[wid] = sum;
    __syncthreads();
    if (t == 0) {
        float s = 0.f;
#pragma unroll
        for (int w = 0; w < 8; w++) s += red[w];
        g_l[(size_t)b * N_SP + i] = s;
    }
}

// ---------------------------------------------------------------------------
// PV: feat = P.V^T. CTA: 128i x 128c, j-chunks of 64, double-buffered.
// Epilogue: out = gamma*feat/l + x.
// ---------------------------------------------------------------------------
__global__ __launch_bounds__(256, 2) void pv_kernel(
    const float* __restrict__ xin, const float* __restrict__ gamma,
    float* __restrict__ out)
{
    extern __shared__ char smx[];
    const u32 PT = 0, VT = 32768;
    u32 sb = s2u(smx);
    int t = threadIdx.x, wid = t >> 5, l = t & 31;
    int c0 = blockIdx.x * 128, i0 = blockIdx.y * 128, b = blockIdx.z;

    const char* pp = (const char*)(g_P  + ((size_t)b * N_SP + i0) * N_SP);
    const char* vp = (const char*)(g_vh + ((size_t)b * C_CH + c0) * N_SP);

    auto load_chunk = [&](int jc, int s) {
        size_t jb = (size_t)jc * 128;
#pragma unroll
        for (int it = 0; it < 4; it++) {
            int z = t + it * 256, r = z >> 3, c = z & 7;
            u32 off = s * 16384 + sw128(r * 128 + c * 16);
            cp16(sb + PT + off, pp + (size_t)r * 8192 + jb + c * 16);
            cp16(sb + VT + off, vp + (size_t)r * 8192 + jb + c * 16);
        }
        cp_commit();
    };

    int wi = wid & 1, wc = wid >> 1;
    int g = l >> 2, t4 = l & 3;

    float acc[4][4][4];
#pragma unroll
    for (int i = 0; i < 4; i++)
#pragma unroll
        for (int j = 0; j < 4; j++)
#pragma unroll
            for (int p = 0; p < 4; p++) acc[i][j][p] = 0.f;

    load_chunk(0, 0);
    for (int it = 0; it < 64; it++) {
        int s = it & 1;
        if (it + 1 < 64) { load_chunk(it + 1, s ^ 1); cp_wait1(); }
        else cp_wait0();
        __syncthreads();
#pragma unroll
        for (int ks = 0; ks < 4; ks++) {
            u32 af[4][4], bf[4][2];
#pragma unroll
            for (int ifr = 0; ifr < 4; ifr++) {
                u32 a = sb + PT + s * 16384 + sw128((wi * 64 + ifr * 16 + (l & 15)) * 128
                                                    + ks * 32 + ((l >> 4) & 1) * 16);
                ldsm4(af[ifr][0], af[ifr][1], af[ifr][2], af[ifr][3], a);
            }
#pragma unroll
            for (int cfr = 0; cfr < 4; cfr++) {
                u32 a = sb + VT + s * 16384 + sw128((wc * 32 + cfr * 8 + (l & 7)) * 128
                                                    + ks * 32 + ((l >> 3) & 1) * 16);
                ldsm2(bf[cfr][0], bf[cfr][1], a);
            }
#pragma unroll
            for (int ifr = 0; ifr < 4; ifr++)
#pragma unroll
                for (int cfr = 0; cfr < 4; cfr++)
                    mma16816(acc[ifr][cfr], af[ifr], bf[cfr]);
        }
        __syncthreads();
    }

    float gam = gamma[0];
    float linv[4][2];
#pragma unroll
    for (int ifr = 0; ifr < 4; ifr++) {
        int i = i0 + wi * 64 + ifr * 16 + g;
        linv[ifr][0] = gam / g_l[(size_t)b * N_SP + i];
        linv[ifr][1] = gam / g_l[(size_t)b * N_SP + i + 8];
    }
#pragma unroll
    for (int ifr = 0; ifr < 4; ifr++) {
        int i = i0 + wi * 64 + ifr * 16 + g;
#pragma unroll
        for (int cfr = 0; cfr < 4; cfr++) {
            int c = c0 + wc * 32 + cfr * 8 + t4 * 2;
            size_t base = ((size_t)b * C_CH + c) * N_SP;
            out[base + i]            = acc[ifr][cfr][0] * linv[ifr][0] + xin[base + i];
            out[base + N_SP + i]     = acc[ifr][cfr][1] * linv[ifr][0] + xin[base + N_SP + i];
            out[base + i + 8]        = acc[ifr][cfr][2] * linv[ifr][1] + xin[base + i + 8];
            out[base + N_SP + i + 8] = acc[ifr][cfr][3] * linv[ifr][1] + xin[base + N_SP + i + 8];
        }
    }
}

// ---------------------------------------------------------------------------
extern "C" void kernel_launch(void* const* d_in, const int* in_sizes, int n_in,
                              void* d_out, int out_size)
{
    const float* x  = (const float*)d_in[0];
    const float* Wq = (const float*)d_in[1];
    const float* bq = (const float*)d_in[2];
    const float* Wk = (const float*)d_in[3];
    const float* bk = (const float*)d_in[4];
    const float* Wv = (const float*)d_in[5];
    const float* bv = (const float*)d_in[6];
    const float* gm = (const float*)d_in[7];
    float* out = (float*)d_out;

    void *wqh, *wql, *wkh, *wkl, *wvh, *wvl;
    cudaGetSymbolAddress(&wqh, g_wqh); cudaGetSymbolAddress(&wql, g_wql);
    cudaGetSymbolAddress(&wkh, g_wkh); cudaGetSymbolAddress(&wkl, g_wkl);
    cudaGetSymbolAddress(&wvh, g_wvh); cudaGetSymbolAddress(&wvl, g_wvl);

    xconv_kernel<<<dim3(128, 16, 4), 256>>>(x);
    wconv_kernel<<<128, 256>>>(Wq, (__half*)wqh, (__half*)wql, 64 * C_CH);
    wconv_kernel<<<128, 256>>>(Wk, (__half*)wkh, (__half*)wkl, 64 * C_CH);
    wconv_kernel<<<1024, 256>>>(Wv, (__half*)wvh, (__half*)wvl, C_CH * C_CH);

    cudaFuncSetAttribute(projqk_kernel, cudaFuncAttributeMaxDynamicSharedMemorySize, 98304);
    projqk_kernel<<<dim3(32, 2, 4), 256, 98304>>>(bq, bk);

    cudaFuncSetAttribute(projv_kernel, cudaFuncAttributeMaxDynamicSharedMemorySize, 65536);
    projv_kernel<<<dim3(32, 4, 4), 256, 65536>>>(bv);

    cudaFuncSetAttribute(sgemm_kernel, cudaFuncAttributeMaxDynamicSharedMemorySize, 65536);
    sgemm_kernel<<<dim3(32, 32, 4), 256, 65536>>>();

    softmax_kernel<<<dim3(4096, 4), 256>>>();

    cudaFuncSetAttribute(pv_kernel, cudaFuncAttributeMaxDynamicSharedMemorySize, 65536);
    pv_kernel<<<dim3(4, 32, 4), 256, 65536>>>(x, gm, out);
}